// round 2
// baseline (speedup 1.0000x reference)
#include <cuda_runtime.h>
#include <stdint.h>

#define N_NODES_MAX 100000
#define E_MAX       1200000
#define NFEAT 64
#define NHID  256
#define NCLASS 40
#define ORDER 8

// ---------------- scratch (device globals; no allocation) ----------------
__device__ __align__(256) float g_h0[N_NODES_MAX * NFEAT];
__device__ __align__(256) float g_h1[N_NODES_MAX * NFEAT];
__device__ __align__(256) float g_y [N_NODES_MAX * NFEAT];
__device__ int   g_cnt [N_NODES_MAX];
__device__ int   g_fill[N_NODES_MAX];
__device__ float g_dinv[N_NODES_MAX];
__device__ int   g_rowptr[N_NODES_MAX + 1];
__device__ int   g_incl[N_NODES_MAX];
__device__ int   g_tilesums[128];
__device__ int   g_col[E_MAX];
__device__ float g_w  [E_MAX];
__device__ int   g_is64;

// ---------------- edge-index dtype detection ----------------
// Reference asks for int64 but JAX without x64 silently produces int32.
// Node ids are < 1e5, so valid int64 entries are < 1e5; int32 data read as
// int64 combines two ids -> >= 2^32 unless the high id happens to be 0
// (prob ~1e-5 per sample; 64 samples make misdetection ~impossible).
__global__ void k_detect(const void* ei) {
    if (threadIdx.x == 0 && blockIdx.x == 0) {
        const unsigned long long* p = (const unsigned long long*)ei;
        int is64 = 1;
        for (int i = 0; i < 64; i++) {
            if (p[i] >= (unsigned long long)N_NODES_MAX) { is64 = 0; break; }
        }
        g_is64 = is64;
    }
}

__device__ __forceinline__ int edge_at(const void* ei, int idx) {
    if (g_is64) return (int)((const long long*)ei)[idx];
    return ((const int*)ei)[idx];
}

// ---------------- preprocessing ----------------
__global__ void k_hist(const void* __restrict__ ei, int E) {
    int e = blockIdx.x * blockDim.x + threadIdx.x;
    if (e < E) atomicAdd(&g_cnt[edge_at(ei, e)], 1);
}

__global__ void k_dinv(int n) {
    int i = blockIdx.x * blockDim.x + threadIdx.x;
    if (i < n) g_dinv[i] = rsqrtf((float)(g_cnt[i] + 1));  // +1 self-loop
}

__global__ void k_scan1(int n) {  // blockDim = 1024, inclusive scan per tile
    __shared__ int s[1024];
    int tid = threadIdx.x;
    int i = blockIdx.x * 1024 + tid;
    int v = (i < n) ? g_cnt[i] : 0;
    s[tid] = v;
    __syncthreads();
    #pragma unroll
    for (int off = 1; off < 1024; off <<= 1) {
        int t = (tid >= off) ? s[tid - off] : 0;
        __syncthreads();
        s[tid] += t;
        __syncthreads();
    }
    if (i < n) g_incl[i] = s[tid];
    if (tid == 1023) g_tilesums[blockIdx.x] = s[1023];
}

__global__ void k_scan2(int ntiles) {  // tiny serial scan of tile sums
    if (threadIdx.x == 0 && blockIdx.x == 0) {
        int run = 0;
        for (int t = 0; t < ntiles; t++) {
            int v = g_tilesums[t];
            g_tilesums[t] = run;
            run += v;
        }
    }
}

__global__ void k_scan3(int n, int E) {  // exclusive rowptr
    int i = blockIdx.x * blockDim.x + threadIdx.x;
    if (i < n) g_rowptr[i] = g_incl[i] - g_cnt[i] + g_tilesums[i >> 10];
    if (i == 0) g_rowptr[n] = E;
}

__global__ void k_scatter(const void* __restrict__ ei, int E) {
    int e = blockIdx.x * blockDim.x + threadIdx.x;
    if (e >= E) return;
    int r = edge_at(ei, e);
    int c = edge_at(ei, E + e);
    int pos = g_rowptr[r] + atomicAdd(&g_fill[r], 1);
    g_col[pos] = c;
    g_w[pos] = g_dinv[r] * g_dinv[c];
}

// ---------------- h0 = y = 0.5 * x ----------------
__global__ void k_init(const float4* __restrict__ x, int n4) {
    int i = blockIdx.x * blockDim.x + threadIdx.x;
    if (i < n4) {
        float4 v = x[i];
        v.x *= 0.5f; v.y *= 0.5f; v.z *= 0.5f; v.w *= 0.5f;
        ((float4*)g_h0)[i] = v;
        ((float4*)g_y)[i]  = v;
    }
}

// ---------------- SPMM: warp-per-row CSR gather, fused y accumulation -----
// Neighbor ids/weights are read with UNIFORM loads (all lanes load the same
// address -> single-sector L1 broadcast) instead of SHFL (26-cyc latency).
// 2x unroll with independent accumulator pairs keeps 2 h[col] gathers in
// flight per warp and halves the FMA RAW chain length.
__global__ __launch_bounds__(256) void k_spmm(const float* __restrict__ hsrc,
                                              float* __restrict__ hdst, int n) {
    int w = (blockIdx.x * blockDim.x + threadIdx.x) >> 5;
    int lane = threadIdx.x & 31;
    if (w >= n) return;
    const float2* __restrict__ hs = (const float2*)hsrc;
    float dv = g_dinv[w];
    float2 hv = hs[w * 32 + lane];
    float sw = dv * dv;            // self-loop weight
    float ax0 = sw * hv.x, ay0 = sw * hv.y;
    float ax1 = 0.f,       ay1 = 0.f;
    int beg = g_rowptr[w], end = g_rowptr[w + 1];
    int j = beg;
    for (; j + 2 <= end; j += 2) {
        int   c0 = __ldg(&g_col[j]);
        int   c1 = __ldg(&g_col[j + 1]);
        float w0 = __ldg(&g_w[j]);
        float w1 = __ldg(&g_w[j + 1]);
        float2 v0 = hs[c0 * 32 + lane];
        float2 v1 = hs[c1 * 32 + lane];
        ax0 = fmaf(w0, v0.x, ax0);
        ay0 = fmaf(w0, v0.y, ay0);
        ax1 = fmaf(w1, v1.x, ax1);
        ay1 = fmaf(w1, v1.y, ay1);
    }
    if (j < end) {
        int   c0 = __ldg(&g_col[j]);
        float w0 = __ldg(&g_w[j]);
        float2 v0 = hs[c0 * 32 + lane];
        ax0 = fmaf(w0, v0.x, ax0);
        ay0 = fmaf(w0, v0.y, ay0);
    }
    float ax = ax0 + ax1, ay = ay0 + ay1;
    float2 a; a.x = ax; a.y = ay;
    ((float2*)hdst)[w * 32 + lane] = a;
    float2* yp = (float2*)g_y;
    float2 yy = yp[w * 32 + lane];
    yy.x += ax; yy.y += ay;
    yp[w * 32 + lane] = yy;
}

// ---------------- fused MLP: relu(y/9 @ W1 + b1) @ W2 + b2 ----------------
// 32 rows per block. W1/W2/y-tile/hid-tile all in shared memory.
#define HID_STRIDE 257  // pad to dodge 4-way bank conflicts in GEMM2 reads
#define SMEM_FLOATS (64*256 + 256*40 + 32*64 + 32*HID_STRIDE + 4*32*40)

__global__ __launch_bounds__(256) void k_mlp(const float* __restrict__ y,
                                             const float* __restrict__ W1,
                                             const float* __restrict__ b1,
                                             const float* __restrict__ W2,
                                             const float* __restrict__ b2,
                                             float* __restrict__ out, int n) {
    extern __shared__ float sm[];
    float* W1s = sm;                    // [64][256]
    float* W2s = W1s + 64 * 256;        // [256][40]
    float* ys  = W2s + 256 * 40;        // [32][64]
    float* hid = ys + 32 * 64;          // [32][HID_STRIDE]
    float* red = hid + 32 * HID_STRIDE; // [4][32][40] split-k partials

    int tid = threadIdx.x;
    int row0 = blockIdx.x * 32;
    const float inv9 = 1.0f / 9.0f;

    for (int i = tid; i < 64 * 256; i += 256) W1s[i] = W1[i];
    for (int i = tid; i < 256 * 40; i += 256) W2s[i] = W2[i];
    for (int i = tid; i < 32 * 64; i += 256) {
        int r = i >> 6, g = row0 + r;
        ys[i] = (g < n) ? y[g * 64 + (i & 63)] * inv9 : 0.f;
    }
    __syncthreads();

    // GEMM1: warp w handles rows 4w..4w+3, lane handles cols lane*8..+7
    int lane = tid & 31, warp = tid >> 5;
    int r0 = warp * 4;
    int c0 = lane * 8;
    float acc[4][8];
    #pragma unroll
    for (int r = 0; r < 4; r++)
        #pragma unroll
        for (int c = 0; c < 8; c++) acc[r][c] = 0.f;

    #pragma unroll 4
    for (int k = 0; k < 64; k++) {
        float4 w0 = *(const float4*)&W1s[k * 256 + c0];
        float4 w1 = *(const float4*)&W1s[k * 256 + c0 + 4];
        #pragma unroll
        for (int r = 0; r < 4; r++) {
            float yv = ys[(r0 + r) * 64 + k];
            acc[r][0] = fmaf(yv, w0.x, acc[r][0]);
            acc[r][1] = fmaf(yv, w0.y, acc[r][1]);
            acc[r][2] = fmaf(yv, w0.z, acc[r][2]);
            acc[r][3] = fmaf(yv, w0.w, acc[r][3]);
            acc[r][4] = fmaf(yv, w1.x, acc[r][4]);
            acc[r][5] = fmaf(yv, w1.y, acc[r][5]);
            acc[r][6] = fmaf(yv, w1.z, acc[r][6]);
            acc[r][7] = fmaf(yv, w1.w, acc[r][7]);
        }
    }
    #pragma unroll
    for (int c = 0; c < 8; c++) {
        float bb = b1[c0 + c];
        #pragma unroll
        for (int r = 0; r < 4; r++)
            hid[(r0 + r) * HID_STRIDE + c0 + c] = fmaxf(acc[r][c] + bb, 0.f);
    }
    __syncthreads();

    // GEMM2, split-k by 4: group g2 covers k in [g2*64, g2*64+64)
    int g2 = tid >> 6;       // 0..3
    int u  = tid & 63;
    int cg = u & 7;          // 5 cols: cg*5..+4
    int rg = u >> 3;         // rows rg*4..+3
    float a2[4][5];
    #pragma unroll
    for (int r = 0; r < 4; r++)
        #pragma unroll
        for (int j = 0; j < 5; j++) a2[r][j] = 0.f;

    #pragma unroll 4
    for (int kk = 0; kk < 64; kk++) {
        int k = g2 * 64 + kk;
        float wv[5];
        #pragma unroll
        for (int j = 0; j < 5; j++) wv[j] = W2s[k * 40 + cg * 5 + j];
        #pragma unroll
        for (int r = 0; r < 4; r++) {
            float hv = hid[(rg * 4 + r) * HID_STRIDE + k];
            #pragma unroll
            for (int j = 0; j < 5; j++) a2[r][j] = fmaf(hv, wv[j], a2[r][j]);
        }
    }
    #pragma unroll
    for (int r = 0; r < 4; r++)
        #pragma unroll
        for (int j = 0; j < 5; j++)
            red[g2 * 1280 + (rg * 4 + r) * 40 + cg * 5 + j] = a2[r][j];
    __syncthreads();

    for (int i = tid; i < 1280; i += 256) {
        int r = i / 40, c = i % 40;
        float s = red[i] + red[1280 + i] + red[2560 + i] + red[3840 + i] + b2[c];
        int g = row0 + r;
        if (g < n) out[g * 40 + c] = s;
    }
}

// ---------------- launch ----------------
extern "C" void kernel_launch(void* const* d_in, const int* in_sizes, int n_in,
                              void* d_out, int out_size) {
    const float* x  = (const float*)d_in[0];
    const void*  ei = d_in[1];
    const float* W1 = (const float*)d_in[2];
    const float* b1 = (const float*)d_in[3];
    const float* W2 = (const float*)d_in[4];
    const float* b2 = (const float*)d_in[5];
    float* out = (float*)d_out;

    int n = in_sizes[0] / NFEAT;   // 100000
    int E = in_sizes[1] / 2;       // 1200000

    void *cntp, *fillp, *h0p, *h1p, *yp;
    cudaGetSymbolAddress(&cntp,  g_cnt);
    cudaGetSymbolAddress(&fillp, g_fill);
    cudaGetSymbolAddress(&h0p,   g_h0);
    cudaGetSymbolAddress(&h1p,   g_h1);
    cudaGetSymbolAddress(&yp,    g_y);

    cudaMemsetAsync(cntp,  0, n * sizeof(int), 0);
    cudaMemsetAsync(fillp, 0, n * sizeof(int), 0);

    k_detect<<<1, 32>>>(ei);
    k_hist<<<(E + 255) / 256, 256>>>(ei, E);
    k_dinv<<<(n + 255) / 256, 256>>>(n);
    int ntiles = (n + 1023) / 1024;
    k_scan1<<<ntiles, 1024>>>(n);
    k_scan2<<<1, 32>>>(ntiles);
    k_scan3<<<(n + 255) / 256, 256>>>(n, E);
    k_scatter<<<(E + 255) / 256, 256>>>(ei, E);

    int n4 = n * NFEAT / 4;
    k_init<<<(n4 + 255) / 256, 256>>>((const float4*)x, n4);

    float* hA = (float*)h0p;
    float* hB = (float*)h1p;
    int spmmBlocks = (n * 32 + 255) / 256;
    for (int it = 0; it < ORDER; it++) {
        k_spmm<<<spmmBlocks, 256>>>(hA, hB, n);
        float* t = hA; hA = hB; hB = t;
    }

    size_t smemBytes = (size_t)SMEM_FLOATS * sizeof(float);  // ~168 KB
    cudaFuncSetAttribute(k_mlp, cudaFuncAttributeMaxDynamicSharedMemorySize,
                         (int)smemBytes);
    k_mlp<<<(n + 31) / 32, 256, smemBytes>>>((const float*)yp, W1, b1, W2, b2,
                                             out, n);
}